// round 6
// baseline (speedup 1.0000x reference)
#include <cuda_runtime.h>
#include <cuda_bf16.h>
#include <cstdint>

#define B_ 4
#define T_ 2048
#define H_ 2048
#define F_ 8192
#define M_ (B_*T_)   // 8192 tokens

// ---------------- device scratch (static; no allocations) ----------------
__device__ __nv_bfloat16 g_wkq[(size_t)F_*H_];   // ternary key weight codes
__device__ __nv_bfloat16 g_wrq[(size_t)H_*H_];   // ternary receptance weight codes
__device__ __nv_bfloat16 g_wvq[(size_t)H_*F_];   // ternary value weight codes
__device__ __nv_bfloat16 g_aK[(size_t)M_*H_];    // int8 codes of key_in (as bf16)
__device__ __nv_bfloat16 g_aR[(size_t)M_*H_];    // int8 codes of rec_in
__device__ __nv_bfloat16 g_aV[(size_t)M_*F_];    // int8 codes of k
__device__ float g_kraw[(size_t)M_*F_];          // k = relu(.)^2, fp32
__device__ float g_rbuf[(size_t)M_*H_];          // sigmoid(receptance)
__device__ float g_sK[M_], g_sR[M_], g_sV[M_];   // per-row dequant scale
__device__ float g_part[3*1024];
__device__ float g_ws[6];                        // [2i]=ws, [2i+1]=1/ws

// ---------------- reductions ----------------
__device__ __forceinline__ float warpSum(float v){
  #pragma unroll
  for(int o=16;o;o>>=1) v += __shfl_xor_sync(0xffffffffu, v, o);
  return v;
}
__device__ __forceinline__ float warpMax(float v){
  #pragma unroll
  for(int o=16;o;o>>=1) v = fmaxf(v, __shfl_xor_sync(0xffffffffu, v, o));
  return v;
}
__device__ __forceinline__ float blkSum(float v, float* sm){
  int t = threadIdx.x, nw = blockDim.x >> 5;
  v = warpSum(v);
  if((t&31)==0) sm[t>>5] = v;
  __syncthreads();
  float r = (t < nw) ? sm[t] : 0.f;
  r = warpSum(r);
  if(t==0) sm[0] = r;
  __syncthreads();
  r = sm[0];
  __syncthreads();
  return r;
}
__device__ __forceinline__ float blkMax(float v, float* sm){
  int t = threadIdx.x, nw = blockDim.x >> 5;
  v = warpMax(v);
  if((t&31)==0) sm[t>>5] = v;
  __syncthreads();
  float r = (t < nw) ? sm[t] : 0.f;
  r = warpMax(r);
  if(t==0) sm[0] = r;
  __syncthreads();
  r = sm[0];
  __syncthreads();
  return r;
}

// ---------------- weight scale: two-stage deterministic mean(|w|) ----------------
__global__ void k_absum(const float* __restrict__ w, int n4, int poff){
  __shared__ float sm[32];
  float s = 0.f;
  const float4* w4 = (const float4*)w;
  for(int i = blockIdx.x*blockDim.x + threadIdx.x; i < n4; i += gridDim.x*blockDim.x){
    float4 v = w4[i];
    s += fabsf(v.x) + fabsf(v.y) + fabsf(v.z) + fabsf(v.w);
  }
  s = blkSum(s, sm);
  if(threadIdx.x == 0) g_part[poff + blockIdx.x] = s;
}

__global__ void k_wsfin(){
  __shared__ float sm[32];
  const float cnts[3] = {(float)((size_t)F_*H_), (float)((size_t)H_*H_), (float)((size_t)H_*F_)};
  for(int i=0;i<3;i++){
    float v = g_part[i*1024 + threadIdx.x];
    float tot = blkSum(v, sm);
    if(threadIdx.x == 0){
      float mean = tot / cnts[i];
      float c = fmaxf(mean, 1e-5f);
      g_ws[2*i]   = 1.f/c;
      g_ws[2*i+1] = c;
    }
    __syncthreads();
  }
}

// ---------------- ternary weight quantization ----------------
__global__ void k_quantw(const float* __restrict__ w, __nv_bfloat16* __restrict__ wq,
                         int n4, int wsidx){
  float ws = g_ws[2*wsidx];
  for(int i = blockIdx.x*blockDim.x + threadIdx.x; i < n4; i += gridDim.x*blockDim.x){
    float4 v = ((const float4*)w)[i];
    float q0 = fminf(fmaxf(rintf(v.x*ws), -1.f), 1.f);
    float q1 = fminf(fmaxf(rintf(v.y*ws), -1.f), 1.f);
    float q2 = fminf(fmaxf(rintf(v.z*ws), -1.f), 1.f);
    float q3 = fminf(fmaxf(rintf(v.w*ws), -1.f), 1.f);
    __nv_bfloat162* o = ((__nv_bfloat162*)wq) + 2*(size_t)i;
    o[0] = __floats2bfloat162_rn(q0, q1);
    o[1] = __floats2bfloat162_rn(q2, q3);
  }
}

// ---------------- token shift + RMSNorm + int8 activation quant ----------------
__global__ void k_actprep(const float* __restrict__ hidden,
                          const float* __restrict__ tmk, const float* __restrict__ tmr,
                          const float* __restrict__ nk,  const float* __restrict__ nr){
  __shared__ float sm[32];
  int m = blockIdx.x;
  int t = m & (T_-1);
  const float* cur = hidden + (size_t)m*H_;
  float kin[8], rin[8];
  float ssk=0.f, ssr=0.f, amk=0.f, amr=0.f;
  #pragma unroll
  for(int j=0;j<8;j++){
    int h = threadIdx.x + j*256;
    float xc = cur[h];
    float xp = (t==0) ? 0.f : cur[h - H_];
    float a = tmk[h], b = tmr[h];
    float ki = xc*a + xp*(1.f-a);
    float ri = xc*b + xp*(1.f-b);
    kin[j]=ki; rin[j]=ri;
    ssk += ki*ki; ssr += ri*ri;
    amk = fmaxf(amk, fabsf(ki*nk[h]));
    amr = fmaxf(amr, fabsf(ri*nr[h]));
  }
  float tssk = blkSum(ssk, sm);
  float tssr = blkSum(ssr, sm);
  float tamk = blkMax(amk, sm);
  float tamr = blkMax(amr, sm);
  float rk = rsqrtf(tssk*(1.f/H_) + 1e-8f);
  float rr = rsqrtf(tssr*(1.f/H_) + 1e-8f);
  float rsK = fmaxf(tamk*rk, 1e-5f);
  float rsR = fmaxf(tamr*rr, 1e-5f);
  float sk = 127.f/rsK, sr = 127.f/rsR;
  #pragma unroll
  for(int j=0;j<8;j++){
    int h = threadIdx.x + j*256;
    float qk = fminf(fmaxf(rintf(kin[j]*nk[h]*rk*sk), -128.f), 127.f);
    float qr = fminf(fmaxf(rintf(rin[j]*nr[h]*rr*sr), -128.f), 127.f);
    g_aK[(size_t)m*H_ + h] = __float2bfloat16(qk);
    g_aR[(size_t)m*H_ + h] = __float2bfloat16(qr);
  }
  if(threadIdx.x == 0){ g_sK[m] = rsK*(1.f/127.f); g_sR[m] = rsR*(1.f/127.f); }
}

// ---------------- RMSNorm + int8 quant of k rows (F=8192) ----------------
__global__ void k_quantK(const float* __restrict__ nv){
  __shared__ float sm[32];
  int m = blockIdx.x;
  const float* row = g_kraw + (size_t)m*F_;
  float v[32];
  float ss=0.f, am=0.f;
  #pragma unroll
  for(int j=0;j<32;j++){
    int h = threadIdx.x + j*256;
    float x = row[h];
    v[j] = x;
    ss += x*x;
    am = fmaxf(am, fabsf(x*nv[h]));
  }
  float tss = blkSum(ss, sm);
  float tam = blkMax(am, sm);
  float rinv = rsqrtf(tss*(1.f/F_) + 1e-8f);
  float rs = fmaxf(tam*rinv, 1e-5f);
  float s = 127.f/rs;
  #pragma unroll
  for(int j=0;j<32;j++){
    int h = threadIdx.x + j*256;
    float q = fminf(fmaxf(rintf(v[j]*nv[h]*rinv*s), -128.f), 127.f);
    g_aV[(size_t)m*F_ + h] = __float2bfloat16(q);
  }
  if(threadIdx.x == 0) g_sV[m] = rs*(1.f/127.f);
}

// ---------------- bf16 tensor-core GEMM: C[M,N] = A[M,K] * Bw[N,K]^T ----------------
// CTA tile 128x256, 8 warps in 2x4, warp tile 64x64
#define BM 128
#define BN 256
#define BKg 64          // 64 bf16 elems = 128 B per row
#define LDT 72          // elems: 64 + 8 pad -> 144B row stride, conflict-free frag LDS
#define NSTAGE 3
#define STAGE_E ((BM+BN)*LDT)           // elems per stage: 27648
#define STAGE_BYTES (STAGE_E*2)         // 55296 B
#define SMEM_TOTAL (NSTAGE*STAGE_BYTES) // 165888 B

__device__ __forceinline__ void cp16(uint32_t s, const void* g){
  asm volatile("cp.async.cg.shared.global [%0], [%1], 16;" :: "r"(s), "l"(g));
}
__device__ __forceinline__ void cp_commit(){ asm volatile("cp.async.commit_group;" ::: "memory"); }
template<int N> __device__ __forceinline__ void cp_wait(){
  asm volatile("cp.async.wait_group %0;" :: "n"(N) : "memory");
}
__device__ __forceinline__ void mma16816(float* c, const uint32_t* a, const uint32_t* b){
  asm volatile(
    "mma.sync.aligned.m16n8k16.row.col.f32.bf16.bf16.f32 "
    "{%0,%1,%2,%3}, {%4,%5,%6,%7}, {%8,%9}, {%0,%1,%2,%3};\n"
    : "+f"(c[0]), "+f"(c[1]), "+f"(c[2]), "+f"(c[3])
    : "r"(a[0]), "r"(a[1]), "r"(a[2]), "r"(a[3]), "r"(b[0]), "r"(b[1]));
}

// MODE 0: key   -> g_kraw = relu(x)^2
// MODE 1: rec   -> g_rbuf = sigmoid(x)
// MODE 2: value -> Cout   = x * g_rbuf
template<int MODE>
__global__ __launch_bounds__(256,1) void k_gemm(float* __restrict__ Cout){
  constexpr int Ndim = (MODE==0) ? F_ : H_;
  constexpr int Kdim = (MODE==2) ? F_ : H_;
  constexpr int NKT  = Kdim / BKg;

  const __nv_bfloat16* __restrict__ A  = (MODE==0) ? g_aK  : (MODE==1) ? g_aR  : g_aV;
  const __nv_bfloat16* __restrict__ Bw = (MODE==0) ? g_wkq : (MODE==1) ? g_wrq : g_wvq;
  const float* __restrict__ rowscale   = (MODE==0) ? g_sK  : (MODE==1) ? g_sR  : g_sV;
  float* __restrict__ C                = (MODE==0) ? g_kraw : (MODE==1) ? g_rbuf : Cout;
  const float wdeq = g_ws[2*((MODE==0)?0:(MODE==1)?1:2) + 1];

  extern __shared__ __align__(128) __nv_bfloat16 smem[];

  const int tid = threadIdx.x;
  const int bm = blockIdx.y*BM, bn = blockIdx.x*BN;

  auto loads = [&](int buf, int kt){
    __nv_bfloat16* st = smem + buf*STAGE_E;
    const __nv_bfloat16* Ak = A  + (size_t)bm*Kdim + kt*BKg;
    const __nv_bfloat16* Bk = Bw + (size_t)bn*Kdim + kt*BKg;
    #pragma unroll
    for(int i=0;i<12;i++){
      int chunk = tid + 256*i;         // 0..3071 : 384 rows x 8 x 16B
      int row = chunk >> 3;
      int kc  = (chunk & 7) << 3;      // elems: 0,8,...,56
      const __nv_bfloat16* gp = (row < BM) ? (Ak + (size_t)row*Kdim + kc)
                                           : (Bk + (size_t)(row-BM)*Kdim + kc);
      cp16((uint32_t)__cvta_generic_to_shared(st + row*LDT + kc), gp);
    }
    cp_commit();
  };

  const int warp = tid >> 5, lane = tid & 31;
  const int wm = (warp & 1) * 64;    // 2 warps in M
  const int wn = (warp >> 1) * 64;   // 4 warps in N
  const int g = lane >> 2, q = lane & 3;

  float acc[4][8][4];
  #pragma unroll
  for(int a0=0;a0<4;a0++)
    #pragma unroll
    for(int b0=0;b0<8;b0++)
      #pragma unroll
      for(int c0=0;c0<4;c0++) acc[a0][b0][c0]=0.f;

  #pragma unroll
  for(int s=0;s<NSTAGE;s++) loads(s, s);

  #pragma unroll 1
  for(int kt=0; kt<NKT; kt++){
    cp_wait<NSTAGE-1>();
    __syncthreads();
    const int buf = kt % NSTAGE;
    const __nv_bfloat16* sA = smem + buf*STAGE_E;
    const __nv_bfloat16* sB = sA + BM*LDT;

    #pragma unroll
    for(int ks=0; ks<4; ks++){
      const int kk = ks*16;
      uint32_t afr[4][4], bfr[8][2];
      #pragma unroll
      for(int mi=0; mi<4; mi++){
        const __nv_bfloat16* base = &sA[(wm + mi*16 + g)*LDT + kk + 2*q];
        afr[mi][0] = *(const uint32_t*)(base);
        afr[mi][1] = *(const uint32_t*)(base + 8*LDT);
        afr[mi][2] = *(const uint32_t*)(base + 8);
        afr[mi][3] = *(const uint32_t*)(base + 8*LDT + 8);
      }
      #pragma unroll
      for(int ni=0; ni<8; ni++){
        const __nv_bfloat16* base = &sB[(wn + ni*8 + g)*LDT + kk + 2*q];
        bfr[ni][0] = *(const uint32_t*)(base);
        bfr[ni][1] = *(const uint32_t*)(base + 8);
      }
      #pragma unroll
      for(int mi=0; mi<4; mi++)
        #pragma unroll
        for(int ni=0; ni<8; ni++)
          mma16816(acc[mi][ni], afr[mi], bfr[ni]);
    }
    __syncthreads();
    if(kt + NSTAGE < NKT) loads(buf, kt + NSTAGE);
    else cp_commit();       // keep group count uniform for cp_wait
  }

  // epilogue
  #pragma unroll
  for(int mi=0; mi<4; mi++){
    int r0 = bm + wm + mi*16 + g;
    int r1 = r0 + 8;
    float sc0 = rowscale[r0]*wdeq;
    float sc1 = rowscale[r1]*wdeq;
    #pragma unroll
    for(int ni=0; ni<8; ni++){
      int col = bn + wn + ni*8 + 2*q;
      float x0 = acc[mi][ni][0]*sc0, x1 = acc[mi][ni][1]*sc0;
      float x2 = acc[mi][ni][2]*sc1, x3 = acc[mi][ni][3]*sc1;
      if(MODE == 0){
        x0 = (x0>0.f)? x0*x0 : 0.f;  x1 = (x1>0.f)? x1*x1 : 0.f;
        x2 = (x2>0.f)? x2*x2 : 0.f;  x3 = (x3>0.f)? x3*x3 : 0.f;
      } else if(MODE == 1){
        x0 = 1.f/(1.f+expf(-x0)); x1 = 1.f/(1.f+expf(-x1));
        x2 = 1.f/(1.f+expf(-x2)); x3 = 1.f/(1.f+expf(-x3));
      } else {
        float2 m0 = *(const float2*)&g_rbuf[(size_t)r0*Ndim + col];
        float2 m1 = *(const float2*)&g_rbuf[(size_t)r1*Ndim + col];
        x0 *= m0.x; x1 *= m0.y; x2 *= m1.x; x3 *= m1.y;
      }
      *(float2*)&C[(size_t)r0*Ndim + col] = make_float2(x0, x1);
      *(float2*)&C[(size_t)r1*Ndim + col] = make_float2(x2, x3);
    }
  }
}

// ---------------- launch ----------------
extern "C" void kernel_launch(void* const* d_in, const int* in_sizes, int n_in,
                              void* d_out, int out_size){
  const float* hidden = (const float*)d_in[0];
  const float* tmk    = (const float*)d_in[1];
  const float* tmr    = (const float*)d_in[2];
  const float* w_key  = (const float*)d_in[3];
  const float* w_rec  = (const float*)d_in[4];
  const float* w_val  = (const float*)d_in[5];
  const float* nk     = (const float*)d_in[6];
  const float* nr     = (const float*)d_in[7];
  const float* nv     = (const float*)d_in[8];
  float* out = (float*)d_out;

  __nv_bfloat16 *wkq, *wrq, *wvq;
  cudaGetSymbolAddress((void**)&wkq, g_wkq);
  cudaGetSymbolAddress((void**)&wrq, g_wrq);
  cudaGetSymbolAddress((void**)&wvq, g_wvq);

  cudaFuncSetAttribute(k_gemm<0>, cudaFuncAttributeMaxDynamicSharedMemorySize, SMEM_TOTAL);
  cudaFuncSetAttribute(k_gemm<1>, cudaFuncAttributeMaxDynamicSharedMemorySize, SMEM_TOTAL);
  cudaFuncSetAttribute(k_gemm<2>, cudaFuncAttributeMaxDynamicSharedMemorySize, SMEM_TOTAL);

  // 1) weight scales
  k_absum<<<1024,256>>>(w_key, (F_*H_)/4, 0);
  k_absum<<<1024,256>>>(w_rec, (H_*H_)/4, 1024);
  k_absum<<<1024,256>>>(w_val, (H_*F_)/4, 2048);
  k_wsfin<<<1,1024>>>();

  // 2) ternary weight codes
  k_quantw<<<4096,256>>>(w_key, wkq, (F_*H_)/4, 0);
  k_quantw<<<1024,256>>>(w_rec, wrq, (H_*H_)/4, 1);
  k_quantw<<<4096,256>>>(w_val, wvq, (H_*F_)/4, 2);

  // 3) token-shift mix + RMSNorm + int8 codes for key_in / rec_in
  k_actprep<<<M_,256>>>(hidden, tmk, tmr, nk, nr);

  // 4) key GEMM -> relu^2 -> k (fp32)
  k_gemm<0><<<dim3(F_/BN, M_/BM), 256, SMEM_TOTAL>>>(nullptr);

  // 5) RMSNorm + int8 codes for k
  k_quantK<<<M_,256>>>(nv);

  // 6) receptance GEMM -> sigmoid -> r
  k_gemm<1><<<dim3(H_/BN, M_/BM), 256, SMEM_TOTAL>>>(nullptr);

  // 7) value GEMM -> * r -> out
  k_gemm<2><<<dim3(H_/BN, M_/BM), 256, SMEM_TOTAL>>>(out);
}

// round 7
// speedup vs baseline: 1.1268x; 1.1268x over previous
#include <cuda_runtime.h>
#include <cuda_bf16.h>
#include <cstdint>

#define B_ 4
#define T_ 2048
#define H_ 2048
#define F_ 8192
#define M_ (B_*T_)   // 8192 tokens

// ---------------- device scratch (static; no allocations) ----------------
__device__ __nv_bfloat16 g_wkq[(size_t)F_*H_];   // ternary key weight codes
__device__ __nv_bfloat16 g_wrq[(size_t)H_*H_];   // ternary receptance weight codes
__device__ __nv_bfloat16 g_wvq[(size_t)H_*F_];   // ternary value weight codes
__device__ __nv_bfloat16 g_aK[(size_t)M_*H_];    // int8 codes of key_in (as bf16)
__device__ __nv_bfloat16 g_aR[(size_t)M_*H_];    // int8 codes of rec_in
__device__ __nv_bfloat16 g_aV[(size_t)M_*F_];    // int8 codes of k
__device__ float g_kraw[(size_t)M_*F_];          // k = relu(.)^2, fp32
__device__ float g_rbuf[(size_t)M_*H_];          // sigmoid(receptance)
__device__ float g_sK[M_], g_sR[M_], g_sV[M_];   // per-row dequant scale
__device__ float g_part[3*1024];
__device__ float g_ws[6];                        // [2i]=ws, [2i+1]=1/ws

// ---------------- reductions ----------------
__device__ __forceinline__ float warpSum(float v){
  #pragma unroll
  for(int o=16;o;o>>=1) v += __shfl_xor_sync(0xffffffffu, v, o);
  return v;
}
__device__ __forceinline__ float warpMax(float v){
  #pragma unroll
  for(int o=16;o;o>>=1) v = fmaxf(v, __shfl_xor_sync(0xffffffffu, v, o));
  return v;
}
__device__ __forceinline__ float blkSum(float v, float* sm){
  int t = threadIdx.x, nw = blockDim.x >> 5;
  v = warpSum(v);
  if((t&31)==0) sm[t>>5] = v;
  __syncthreads();
  float r = (t < nw) ? sm[t] : 0.f;
  r = warpSum(r);
  if(t==0) sm[0] = r;
  __syncthreads();
  r = sm[0];
  __syncthreads();
  return r;
}
__device__ __forceinline__ float blkMax(float v, float* sm){
  int t = threadIdx.x, nw = blockDim.x >> 5;
  v = warpMax(v);
  if((t&31)==0) sm[t>>5] = v;
  __syncthreads();
  float r = (t < nw) ? sm[t] : 0.f;
  r = warpMax(r);
  if(t==0) sm[0] = r;
  __syncthreads();
  r = sm[0];
  __syncthreads();
  return r;
}

// ---------------- weight scale: two-stage deterministic mean(|w|) ----------------
__global__ void k_absum(const float* __restrict__ w, int n4, int poff){
  __shared__ float sm[32];
  float s = 0.f;
  const float4* w4 = (const float4*)w;
  for(int i = blockIdx.x*blockDim.x + threadIdx.x; i < n4; i += gridDim.x*blockDim.x){
    float4 v = w4[i];
    s += fabsf(v.x) + fabsf(v.y) + fabsf(v.z) + fabsf(v.w);
  }
  s = blkSum(s, sm);
  if(threadIdx.x == 0) g_part[poff + blockIdx.x] = s;
}

__global__ void k_wsfin(){
  __shared__ float sm[32];
  const float cnts[3] = {(float)((size_t)F_*H_), (float)((size_t)H_*H_), (float)((size_t)H_*F_)};
  for(int i=0;i<3;i++){
    float v = g_part[i*1024 + threadIdx.x];
    float tot = blkSum(v, sm);
    if(threadIdx.x == 0){
      float mean = tot / cnts[i];
      float c = fmaxf(mean, 1e-5f);
      g_ws[2*i]   = 1.f/c;
      g_ws[2*i+1] = c;
    }
    __syncthreads();
  }
}

// ---------------- ternary weight quantization ----------------
__global__ void k_quantw(const float* __restrict__ w, __nv_bfloat16* __restrict__ wq,
                         int n4, int wsidx){
  float ws = g_ws[2*wsidx];
  for(int i = blockIdx.x*blockDim.x + threadIdx.x; i < n4; i += gridDim.x*blockDim.x){
    float4 v = ((const float4*)w)[i];
    float q0 = fminf(fmaxf(rintf(v.x*ws), -1.f), 1.f);
    float q1 = fminf(fmaxf(rintf(v.y*ws), -1.f), 1.f);
    float q2 = fminf(fmaxf(rintf(v.z*ws), -1.f), 1.f);
    float q3 = fminf(fmaxf(rintf(v.w*ws), -1.f), 1.f);
    __nv_bfloat162* o = ((__nv_bfloat162*)wq) + 2*(size_t)i;
    o[0] = __floats2bfloat162_rn(q0, q1);
    o[1] = __floats2bfloat162_rn(q2, q3);
  }
}

// ---------------- token shift + RMSNorm + int8 activation quant ----------------
__global__ void k_actprep(const float* __restrict__ hidden,
                          const float* __restrict__ tmk, const float* __restrict__ tmr,
                          const float* __restrict__ nk,  const float* __restrict__ nr){
  __shared__ float sm[32];
  int m = blockIdx.x;
  int t = m & (T_-1);
  const float* cur = hidden + (size_t)m*H_;
  float kin[8], rin[8];
  float ssk=0.f, ssr=0.f, amk=0.f, amr=0.f;
  #pragma unroll
  for(int j=0;j<8;j++){
    int h = threadIdx.x + j*256;
    float xc = cur[h];
    float xp = (t==0) ? 0.f : cur[h - H_];
    float a = tmk[h], b = tmr[h];
    float ki = xc*a + xp*(1.f-a);
    float ri = xc*b + xp*(1.f-b);
    kin[j]=ki; rin[j]=ri;
    ssk += ki*ki; ssr += ri*ri;
    amk = fmaxf(amk, fabsf(ki*nk[h]));
    amr = fmaxf(amr, fabsf(ri*nr[h]));
  }
  float tssk = blkSum(ssk, sm);
  float tssr = blkSum(ssr, sm);
  float tamk = blkMax(amk, sm);
  float tamr = blkMax(amr, sm);
  float rk = rsqrtf(tssk*(1.f/H_) + 1e-8f);
  float rr = rsqrtf(tssr*(1.f/H_) + 1e-8f);
  float rsK = fmaxf(tamk*rk, 1e-5f);
  float rsR = fmaxf(tamr*rr, 1e-5f);
  float sk = 127.f/rsK, sr = 127.f/rsR;
  #pragma unroll
  for(int j=0;j<8;j++){
    int h = threadIdx.x + j*256;
    float qk = fminf(fmaxf(rintf(kin[j]*nk[h]*rk*sk), -128.f), 127.f);
    float qr = fminf(fmaxf(rintf(rin[j]*nr[h]*rr*sr), -128.f), 127.f);
    g_aK[(size_t)m*H_ + h] = __float2bfloat16(qk);
    g_aR[(size_t)m*H_ + h] = __float2bfloat16(qr);
  }
  if(threadIdx.x == 0){ g_sK[m] = rsK*(1.f/127.f); g_sR[m] = rsR*(1.f/127.f); }
}

// ---------------- RMSNorm + int8 quant of k rows (F=8192) ----------------
__global__ void k_quantK(const float* __restrict__ nv){
  __shared__ float sm[32];
  int m = blockIdx.x;
  const float* row = g_kraw + (size_t)m*F_;
  float v[32];
  float ss=0.f, am=0.f;
  #pragma unroll
  for(int j=0;j<32;j++){
    int h = threadIdx.x + j*256;
    float x = row[h];
    v[j] = x;
    ss += x*x;
    am = fmaxf(am, fabsf(x*nv[h]));
  }
  float tss = blkSum(ss, sm);
  float tam = blkMax(am, sm);
  float rinv = rsqrtf(tss*(1.f/F_) + 1e-8f);
  float rs = fmaxf(tam*rinv, 1e-5f);
  float s = 127.f/rs;
  #pragma unroll
  for(int j=0;j<32;j++){
    int h = threadIdx.x + j*256;
    float q = fminf(fmaxf(rintf(v[j]*nv[h]*rinv*s), -128.f), 127.f);
    g_aV[(size_t)m*F_ + h] = __float2bfloat16(q);
  }
  if(threadIdx.x == 0) g_sV[m] = rs*(1.f/127.f);
}

// ---------------- bf16 tensor-core GEMM: C[M,N] = A[M,K] * Bw[N,K]^T ----------------
// CTA tile 128x128, 4 warps in 2x2, warp tile 64x64, 2 CTAs/SM
#define BM 128
#define BN 128
#define BKg 64          // 64 bf16 elems = 128 B per row
#define LDT 72          // elems: 64 + 8 pad -> 144B row stride, conflict-free frag LDS
#define NSTAGE 3
#define NTHR 128
#define STAGE_E ((BM+BN)*LDT)           // elems per stage: 18432
#define STAGE_BYTES (STAGE_E*2)         // 36864 B
#define SMEM_TOTAL (NSTAGE*STAGE_BYTES) // 110592 B

__device__ __forceinline__ void cp16(uint32_t s, const void* g){
  asm volatile("cp.async.cg.shared.global [%0], [%1], 16;" :: "r"(s), "l"(g));
}
__device__ __forceinline__ void cp_commit(){ asm volatile("cp.async.commit_group;" ::: "memory"); }
template<int N> __device__ __forceinline__ void cp_wait(){
  asm volatile("cp.async.wait_group %0;" :: "n"(N) : "memory");
}
__device__ __forceinline__ void mma16816(float* c, const uint32_t* a, const uint32_t* b){
  asm volatile(
    "mma.sync.aligned.m16n8k16.row.col.f32.bf16.bf16.f32 "
    "{%0,%1,%2,%3}, {%4,%5,%6,%7}, {%8,%9}, {%0,%1,%2,%3};\n"
    : "+f"(c[0]), "+f"(c[1]), "+f"(c[2]), "+f"(c[3])
    : "r"(a[0]), "r"(a[1]), "r"(a[2]), "r"(a[3]), "r"(b[0]), "r"(b[1]));
}

// MODE 0: key   -> g_kraw = relu(x)^2
// MODE 1: rec   -> g_rbuf = sigmoid(x)
// MODE 2: value -> Cout   = x * g_rbuf
template<int MODE>
__global__ __launch_bounds__(NTHR,2) void k_gemm(float* __restrict__ Cout){
  constexpr int Ndim = (MODE==0) ? F_ : H_;
  constexpr int Kdim = (MODE==2) ? F_ : H_;
  constexpr int NKT  = Kdim / BKg;

  const __nv_bfloat16* __restrict__ A  = (MODE==0) ? g_aK  : (MODE==1) ? g_aR  : g_aV;
  const __nv_bfloat16* __restrict__ Bw = (MODE==0) ? g_wkq : (MODE==1) ? g_wrq : g_wvq;
  const float* __restrict__ rowscale   = (MODE==0) ? g_sK  : (MODE==1) ? g_sR  : g_sV;
  float* __restrict__ C                = (MODE==0) ? g_kraw : (MODE==1) ? g_rbuf : Cout;
  const float wdeq = g_ws[2*((MODE==0)?0:(MODE==1)?1:2) + 1];

  extern __shared__ __align__(128) __nv_bfloat16 smem[];

  const int tid = threadIdx.x;
  const int bm = blockIdx.y*BM, bn = blockIdx.x*BN;

  auto loads = [&](int buf, int kt){
    __nv_bfloat16* st = smem + buf*STAGE_E;
    const __nv_bfloat16* Ak = A  + (size_t)bm*Kdim + kt*BKg;
    const __nv_bfloat16* Bk = Bw + (size_t)bn*Kdim + kt*BKg;
    #pragma unroll
    for(int i=0;i<16;i++){
      int chunk = tid + NTHR*i;        // 0..2047 : 256 rows x 8 x 16B
      int row = chunk >> 3;
      int kc  = (chunk & 7) << 3;      // elems: 0,8,...,56
      const __nv_bfloat16* gp = (row < BM) ? (Ak + (size_t)row*Kdim + kc)
                                           : (Bk + (size_t)(row-BM)*Kdim + kc);
      cp16((uint32_t)__cvta_generic_to_shared(st + row*LDT + kc), gp);
    }
    cp_commit();
  };

  const int warp = tid >> 5, lane = tid & 31;
  const int wm = (warp & 1) * 64;    // 2 warps in M
  const int wn = (warp >> 1) * 64;   // 2 warps in N
  const int g = lane >> 2, q = lane & 3;

  float acc[4][8][4];
  #pragma unroll
  for(int a0=0;a0<4;a0++)
    #pragma unroll
    for(int b0=0;b0<8;b0++)
      #pragma unroll
      for(int c0=0;c0<4;c0++) acc[a0][b0][c0]=0.f;

  #pragma unroll
  for(int s=0;s<NSTAGE;s++) loads(s, s);

  #pragma unroll 1
  for(int kt=0; kt<NKT; kt++){
    cp_wait<NSTAGE-1>();
    __syncthreads();
    const int buf = kt % NSTAGE;
    const __nv_bfloat16* sA = smem + buf*STAGE_E;
    const __nv_bfloat16* sB = sA + BM*LDT;

    #pragma unroll
    for(int ks=0; ks<4; ks++){
      const int kk = ks*16;
      uint32_t afr[4][4], bfr[8][2];
      #pragma unroll
      for(int mi=0; mi<4; mi++){
        const __nv_bfloat16* base = &sA[(wm + mi*16 + g)*LDT + kk + 2*q];
        afr[mi][0] = *(const uint32_t*)(base);
        afr[mi][1] = *(const uint32_t*)(base + 8*LDT);
        afr[mi][2] = *(const uint32_t*)(base + 8);
        afr[mi][3] = *(const uint32_t*)(base + 8*LDT + 8);
      }
      #pragma unroll
      for(int ni=0; ni<8; ni++){
        const __nv_bfloat16* base = &sB[(wn + ni*8 + g)*LDT + kk + 2*q];
        bfr[ni][0] = *(const uint32_t*)(base);
        bfr[ni][1] = *(const uint32_t*)(base + 8);
      }
      #pragma unroll
      for(int mi=0; mi<4; mi++)
        #pragma unroll
        for(int ni=0; ni<8; ni++)
          mma16816(acc[mi][ni], afr[mi], bfr[ni]);
    }
    __syncthreads();
    if(kt + NSTAGE < NKT) loads(buf, kt + NSTAGE);
    else cp_commit();       // keep group count uniform for cp_wait
  }

  // epilogue
  #pragma unroll
  for(int mi=0; mi<4; mi++){
    int r0 = bm + wm + mi*16 + g;
    int r1 = r0 + 8;
    float sc0 = rowscale[r0]*wdeq;
    float sc1 = rowscale[r1]*wdeq;
    #pragma unroll
    for(int ni=0; ni<8; ni++){
      int col = bn + wn + ni*8 + 2*q;
      float x0 = acc[mi][ni][0]*sc0, x1 = acc[mi][ni][1]*sc0;
      float x2 = acc[mi][ni][2]*sc1, x3 = acc[mi][ni][3]*sc1;
      if(MODE == 0){
        x0 = (x0>0.f)? x0*x0 : 0.f;  x1 = (x1>0.f)? x1*x1 : 0.f;
        x2 = (x2>0.f)? x2*x2 : 0.f;  x3 = (x3>0.f)? x3*x3 : 0.f;
      } else if(MODE == 1){
        x0 = 1.f/(1.f+expf(-x0)); x1 = 1.f/(1.f+expf(-x1));
        x2 = 1.f/(1.f+expf(-x2)); x3 = 1.f/(1.f+expf(-x3));
      } else {
        float2 m0 = *(const float2*)&g_rbuf[(size_t)r0*Ndim + col];
        float2 m1 = *(const float2*)&g_rbuf[(size_t)r1*Ndim + col];
        x0 *= m0.x; x1 *= m0.y; x2 *= m1.x; x3 *= m1.y;
      }
      *(float2*)&C[(size_t)r0*Ndim + col] = make_float2(x0, x1);
      *(float2*)&C[(size_t)r1*Ndim + col] = make_float2(x2, x3);
    }
  }
}

// ---------------- launch ----------------
extern "C" void kernel_launch(void* const* d_in, const int* in_sizes, int n_in,
                              void* d_out, int out_size){
  const float* hidden = (const float*)d_in[0];
  const float* tmk    = (const float*)d_in[1];
  const float* tmr    = (const float*)d_in[2];
  const float* w_key  = (const float*)d_in[3];
  const float* w_rec  = (const float*)d_in[4];
  const float* w_val  = (const float*)d_in[5];
  const float* nk     = (const float*)d_in[6];
  const float* nr     = (const float*)d_in[7];
  const float* nv     = (const float*)d_in[8];
  float* out = (float*)d_out;

  __nv_bfloat16 *wkq, *wrq, *wvq;
  cudaGetSymbolAddress((void**)&wkq, g_wkq);
  cudaGetSymbolAddress((void**)&wrq, g_wrq);
  cudaGetSymbolAddress((void**)&wvq, g_wvq);

  cudaFuncSetAttribute(k_gemm<0>, cudaFuncAttributeMaxDynamicSharedMemorySize, SMEM_TOTAL);
  cudaFuncSetAttribute(k_gemm<1>, cudaFuncAttributeMaxDynamicSharedMemorySize, SMEM_TOTAL);
  cudaFuncSetAttribute(k_gemm<2>, cudaFuncAttributeMaxDynamicSharedMemorySize, SMEM_TOTAL);

  // 1) weight scales
  k_absum<<<1024,256>>>(w_key, (F_*H_)/4, 0);
  k_absum<<<1024,256>>>(w_rec, (H_*H_)/4, 1024);
  k_absum<<<1024,256>>>(w_val, (H_*F_)/4, 2048);
  k_wsfin<<<1,1024>>>();

  // 2) ternary weight codes
  k_quantw<<<4096,256>>>(w_key, wkq, (F_*H_)/4, 0);
  k_quantw<<<1024,256>>>(w_rec, wrq, (H_*H_)/4, 1);
  k_quantw<<<4096,256>>>(w_val, wvq, (H_*F_)/4, 2);

  // 3) token-shift mix + RMSNorm + int8 codes for key_in / rec_in
  k_actprep<<<M_,256>>>(hidden, tmk, tmr, nk, nr);

  // 4) key GEMM -> relu^2 -> k (fp32)
  k_gemm<0><<<dim3(F_/BN, M_/BM), NTHR, SMEM_TOTAL>>>(nullptr);

  // 5) RMSNorm + int8 codes for k
  k_quantK<<<M_,256>>>(nv);

  // 6) receptance GEMM -> sigmoid -> r
  k_gemm<1><<<dim3(H_/BN, M_/BM), NTHR, SMEM_TOTAL>>>(nullptr);

  // 7) value GEMM -> * r -> out
  k_gemm<2><<<dim3(H_/BN, M_/BM), NTHR, SMEM_TOTAL>>>(out);
}

// round 8
// speedup vs baseline: 1.1301x; 1.0029x over previous
#include <cuda_runtime.h>
#include <cuda_bf16.h>
#include <cstdint>

#define B_ 4
#define T_ 2048
#define H_ 2048
#define F_ 8192
#define M_ (B_*T_)   // 8192 tokens

// ---------------- device scratch (static; no allocations) ----------------
__device__ __nv_bfloat16 g_wkq[(size_t)F_*H_];   // ternary key weight codes
__device__ __nv_bfloat16 g_wrq[(size_t)H_*H_];   // ternary receptance weight codes
__device__ __nv_bfloat16 g_wvq[(size_t)H_*F_];   // ternary value weight codes
__device__ __nv_bfloat16 g_aK[(size_t)M_*H_];    // int8 codes of key_in (as bf16)
__device__ __nv_bfloat16 g_aR[(size_t)M_*H_];    // int8 codes of rec_in
__device__ __nv_bfloat16 g_aV[(size_t)M_*F_];    // int8 codes of k
__device__ float g_kraw[(size_t)M_*F_];          // k = relu(.)^2, fp32
__device__ float g_rbuf[(size_t)M_*H_];          // sigmoid(receptance)
__device__ float g_sK[M_], g_sR[M_], g_sV[M_];   // per-row dequant scale
__device__ float g_part[3*1024];

// ---------------- reductions ----------------
__device__ __forceinline__ float warpSum(float v){
  #pragma unroll
  for(int o=16;o;o>>=1) v += __shfl_xor_sync(0xffffffffu, v, o);
  return v;
}
__device__ __forceinline__ float warpMax(float v){
  #pragma unroll
  for(int o=16;o;o>>=1) v = fmaxf(v, __shfl_xor_sync(0xffffffffu, v, o));
  return v;
}
__device__ __forceinline__ float blkSum(float v, float* sm){
  int t = threadIdx.x, nw = blockDim.x >> 5;
  v = warpSum(v);
  if((t&31)==0) sm[t>>5] = v;
  __syncthreads();
  float r = (t < nw) ? sm[t] : 0.f;
  r = warpSum(r);
  if(t==0) sm[0] = r;
  __syncthreads();
  r = sm[0];
  __syncthreads();
  return r;
}
__device__ __forceinline__ float blkMax(float v, float* sm){
  int t = threadIdx.x, nw = blockDim.x >> 5;
  v = warpMax(v);
  if((t&31)==0) sm[t>>5] = v;
  __syncthreads();
  float r = (t < nw) ? sm[t] : 0.f;
  r = warpMax(r);
  if(t==0) sm[0] = r;
  __syncthreads();
  r = sm[0];
  __syncthreads();
  return r;
}

// ---------------- weight |w| partial sums: all 3 weights in one launch ----------------
__global__ void k_absum_all(const float* __restrict__ wk, const float* __restrict__ wr,
                            const float* __restrict__ wv){
  __shared__ float sm[32];
  int region = blockIdx.x >> 10;           // 0..2
  int lb     = blockIdx.x & 1023;
  const float* w = (region==0) ? wk : (region==1) ? wr : wv;
  int n4 = (region==0) ? (F_*H_)/4 : (region==1) ? (H_*H_)/4 : (H_*F_)/4;
  float s = 0.f;
  const float4* w4 = (const float4*)w;
  for(int i = lb*blockDim.x + threadIdx.x; i < n4; i += 1024*blockDim.x){
    float4 v = w4[i];
    s += fabsf(v.x) + fabsf(v.y) + fabsf(v.z) + fabsf(v.w);
  }
  s = blkSum(s, sm);
  if(threadIdx.x == 0) g_part[region*1024 + lb] = s;
}

// ---------------- ternary weight quantization (ws reduced per-block) ----------------
__global__ void k_quantw_all(const float* __restrict__ wk, const float* __restrict__ wr,
                             const float* __restrict__ wv){
  __shared__ float sm[32];
  int b = blockIdx.x;
  int region, lb, nblk;
  if(b < 4096){ region=0; lb=b; nblk=4096; }
  else if(b < 5120){ region=1; lb=b-4096; nblk=1024; }
  else { region=2; lb=b-5120; nblk=4096; }
  const float* w = (region==0) ? wk : (region==1) ? wr : wv;
  __nv_bfloat16* wq = (region==0) ? g_wkq : (region==1) ? g_wrq : g_wvq;
  int n4 = (region==0) ? (F_*H_)/4 : (region==1) ? (H_*H_)/4 : (H_*F_)/4;
  float cnt = (float)((size_t)n4*4);

  // reduce the 1024 partials for this region (cheap, deterministic)
  float p = 0.f;
  #pragma unroll
  for(int j=0;j<4;j++) p += g_part[region*1024 + threadIdx.x + j*256];
  float tot = blkSum(p, sm);
  float ws = 1.f / fmaxf(tot/cnt, 1e-5f);

  for(int i = lb*blockDim.x + threadIdx.x; i < n4; i += nblk*blockDim.x){
    float4 v = ((const float4*)w)[i];
    float q0 = fminf(fmaxf(rintf(v.x*ws), -1.f), 1.f);
    float q1 = fminf(fmaxf(rintf(v.y*ws), -1.f), 1.f);
    float q2 = fminf(fmaxf(rintf(v.z*ws), -1.f), 1.f);
    float q3 = fminf(fmaxf(rintf(v.w*ws), -1.f), 1.f);
    __nv_bfloat162* o = ((__nv_bfloat162*)wq) + 2*(size_t)i;
    o[0] = __floats2bfloat162_rn(q0, q1);
    o[1] = __floats2bfloat162_rn(q2, q3);
  }
}

// helper for GEMM: wdeq = 1/ws recomputed per block (uniform, deterministic)
__device__ __forceinline__ float wdeq_of(int region, float* sm){
  float p = 0.f;
  if(threadIdx.x < 256){
    #pragma unroll
    for(int j=0;j<4;j++) p += g_part[region*1024 + (threadIdx.x&255) + j*256];
  }
  // blockDim may be 128: cover all 1024 entries
  p = 0.f;
  for(int i = threadIdx.x; i < 1024; i += blockDim.x) p += g_part[region*1024 + i];
  float tot = blkSum(p, sm);
  float cnt = (region==0) ? (float)((size_t)F_*H_) : (region==1) ? (float)((size_t)H_*H_) : (float)((size_t)H_*F_);
  return fmaxf(tot/cnt, 1e-5f);
}

// ---------------- token shift + RMSNorm + int8 activation quant ----------------
__global__ void k_actprep(const float* __restrict__ hidden,
                          const float* __restrict__ tmk, const float* __restrict__ tmr,
                          const float* __restrict__ nk,  const float* __restrict__ nr){
  __shared__ float sm[32];
  int m = blockIdx.x;
  int t = m & (T_-1);
  const float* cur = hidden + (size_t)m*H_;
  float kin[8], rin[8];
  float ssk=0.f, ssr=0.f, amk=0.f, amr=0.f;
  #pragma unroll
  for(int j=0;j<8;j++){
    int h = threadIdx.x + j*256;
    float xc = cur[h];
    float xp = (t==0) ? 0.f : cur[h - H_];
    float a = tmk[h], b = tmr[h];
    float ki = xc*a + xp*(1.f-a);
    float ri = xc*b + xp*(1.f-b);
    kin[j]=ki; rin[j]=ri;
    ssk += ki*ki; ssr += ri*ri;
    amk = fmaxf(amk, fabsf(ki*nk[h]));
    amr = fmaxf(amr, fabsf(ri*nr[h]));
  }
  float tssk = blkSum(ssk, sm);
  float tssr = blkSum(ssr, sm);
  float tamk = blkMax(amk, sm);
  float tamr = blkMax(amr, sm);
  float rk = rsqrtf(tssk*(1.f/H_) + 1e-8f);
  float rr = rsqrtf(tssr*(1.f/H_) + 1e-8f);
  float rsK = fmaxf(tamk*rk, 1e-5f);
  float rsR = fmaxf(tamr*rr, 1e-5f);
  float sk = 127.f/rsK, sr = 127.f/rsR;
  #pragma unroll
  for(int j=0;j<8;j++){
    int h = threadIdx.x + j*256;
    float qk = fminf(fmaxf(rintf(kin[j]*nk[h]*rk*sk), -128.f), 127.f);
    float qr = fminf(fmaxf(rintf(rin[j]*nr[h]*rr*sr), -128.f), 127.f);
    g_aK[(size_t)m*H_ + h] = __float2bfloat16(qk);
    g_aR[(size_t)m*H_ + h] = __float2bfloat16(qr);
  }
  if(threadIdx.x == 0){ g_sK[m] = rsK*(1.f/127.f); g_sR[m] = rsR*(1.f/127.f); }
}

// ---------------- RMSNorm + int8 quant of k rows (F=8192) ----------------
__global__ void k_quantK(const float* __restrict__ nv){
  __shared__ float sm[32];
  int m = blockIdx.x;
  const float* row = g_kraw + (size_t)m*F_;
  float v[32];
  float ss=0.f, am=0.f;
  #pragma unroll
  for(int j=0;j<32;j++){
    int h = threadIdx.x + j*256;
    float x = row[h];
    v[j] = x;
    ss += x*x;
    am = fmaxf(am, fabsf(x*nv[h]));
  }
  float tss = blkSum(ss, sm);
  float tam = blkMax(am, sm);
  float rinv = rsqrtf(tss*(1.f/F_) + 1e-8f);
  float rs = fmaxf(tam*rinv, 1e-5f);
  float s = 127.f/rs;
  #pragma unroll
  for(int j=0;j<32;j++){
    int h = threadIdx.x + j*256;
    float q = fminf(fmaxf(rintf(v[j]*nv[h]*rinv*s), -128.f), 127.f);
    g_aV[(size_t)m*F_ + h] = __float2bfloat16(q);
  }
  if(threadIdx.x == 0) g_sV[m] = rs*(1.f/127.f);
}

// ---------------- bf16 tensor-core GEMM: C[M,N] = A[M,K] * Bw[N,K]^T ----------------
// CTA tile 128x128, 4 warps in 2x2, warp tile 64x64, 2 CTAs/SM,
// single-barrier 3-stage pipeline, ldmatrix.x4 fragment loads
#define BM 128
#define BN 128
#define BKg 64          // 64 bf16 elems = 128 B per row
#define LDT 72          // elems: 64 + 8 pad -> 144B row stride, conflict-free
#define NSTAGE 3
#define NTHR 128
#define STAGE_E ((BM+BN)*LDT)           // elems per stage: 18432
#define STAGE_BYTES (STAGE_E*2)         // 36864 B
#define SMEM_TOTAL (NSTAGE*STAGE_BYTES) // 110592 B

__device__ __forceinline__ void cp16(uint32_t s, const void* g){
  asm volatile("cp.async.cg.shared.global [%0], [%1], 16;" :: "r"(s), "l"(g));
}
__device__ __forceinline__ void cp_commit(){ asm volatile("cp.async.commit_group;" ::: "memory"); }
template<int N> __device__ __forceinline__ void cp_wait(){
  asm volatile("cp.async.wait_group %0;" :: "n"(N) : "memory");
}
__device__ __forceinline__ void ldsm4(uint32_t& r0, uint32_t& r1, uint32_t& r2, uint32_t& r3,
                                      uint32_t addr){
  asm volatile("ldmatrix.sync.aligned.m8n8.x4.shared.b16 {%0,%1,%2,%3}, [%4];"
               : "=r"(r0), "=r"(r1), "=r"(r2), "=r"(r3) : "r"(addr));
}
__device__ __forceinline__ void mma16816(float* c, const uint32_t* a, const uint32_t* b){
  asm volatile(
    "mma.sync.aligned.m16n8k16.row.col.f32.bf16.bf16.f32 "
    "{%0,%1,%2,%3}, {%4,%5,%6,%7}, {%8,%9}, {%0,%1,%2,%3};\n"
    : "+f"(c[0]), "+f"(c[1]), "+f"(c[2]), "+f"(c[3])
    : "r"(a[0]), "r"(a[1]), "r"(a[2]), "r"(a[3]), "r"(b[0]), "r"(b[1]));
}

// MODE 0: key   -> g_kraw = relu(x)^2
// MODE 1: rec   -> g_rbuf = sigmoid(x)
// MODE 2: value -> Cout   = x * g_rbuf
template<int MODE>
__global__ __launch_bounds__(NTHR,2) void k_gemm(float* __restrict__ Cout){
  constexpr int Ndim = (MODE==0) ? F_ : H_;
  constexpr int Kdim = (MODE==2) ? F_ : H_;
  constexpr int NKT  = Kdim / BKg;
  constexpr int REGION = (MODE==0) ? 0 : (MODE==1) ? 1 : 2;

  const __nv_bfloat16* __restrict__ A  = (MODE==0) ? g_aK  : (MODE==1) ? g_aR  : g_aV;
  const __nv_bfloat16* __restrict__ Bw = (MODE==0) ? g_wkq : (MODE==1) ? g_wrq : g_wvq;
  const float* __restrict__ rowscale   = (MODE==0) ? g_sK  : (MODE==1) ? g_sR  : g_sV;
  float* __restrict__ C                = (MODE==0) ? g_kraw : (MODE==1) ? g_rbuf : Cout;

  extern __shared__ __align__(128) __nv_bfloat16 smem[];
  __shared__ float smr[32];

  const int tid = threadIdx.x;
  const int bm = blockIdx.y*BM, bn = blockIdx.x*BN;

  // per-tensor dequant scale (uniform across block; deterministic)
  const float wdeq = wdeq_of(REGION, smr);

  auto loads = [&](int buf, int kt){
    __nv_bfloat16* st = smem + buf*STAGE_E;
    const __nv_bfloat16* Ak = A  + (size_t)bm*Kdim + kt*BKg;
    const __nv_bfloat16* Bk = Bw + (size_t)bn*Kdim + kt*BKg;
    #pragma unroll
    for(int i=0;i<16;i++){
      int chunk = tid + NTHR*i;        // 0..2047 : 256 rows x 8 x 16B
      int row = chunk >> 3;
      int kc  = (chunk & 7) << 3;      // elems: 0,8,...,56
      const __nv_bfloat16* gp = (row < BM) ? (Ak + (size_t)row*Kdim + kc)
                                           : (Bk + (size_t)(row-BM)*Kdim + kc);
      cp16((uint32_t)__cvta_generic_to_shared(st + row*LDT + kc), gp);
    }
    cp_commit();
  };

  const int warp = tid >> 5, lane = tid & 31;
  const int wm = (warp & 1) * 64;    // 2 warps in M
  const int wn = (warp >> 1) * 64;   // 2 warps in N
  const int g = lane >> 2, q = lane & 3;

  const uint32_t sbu = (uint32_t)__cvta_generic_to_shared(smem);
  // ldmatrix per-thread element offsets
  const int aoff = (wm + (lane & 15))*LDT + ((lane >> 4) << 3);
  const int boff = (wn + (lane & 7) + ((lane >> 4) << 3))*LDT + (((lane >> 3) & 1) << 3);

  float acc[4][8][4];
  #pragma unroll
  for(int a0=0;a0<4;a0++)
    #pragma unroll
    for(int b0=0;b0<8;b0++)
      #pragma unroll
      for(int c0=0;c0<4;c0++) acc[a0][b0][c0]=0.f;

  // prefill NSTAGE-1 stages
  loads(0, 0);
  loads(1, 1);

  #pragma unroll 1
  for(int kt=0; kt<NKT; kt++){
    cp_wait<NSTAGE-2>();               // stage kt complete
    __syncthreads();                   // all warps: stage kt visible, stage kt-1 free
    if(kt + NSTAGE - 1 < NKT) loads((kt + NSTAGE - 1) % NSTAGE, kt + NSTAGE - 1);
    else cp_commit();                  // keep group count uniform

    const int buf = kt % NSTAGE;
    const uint32_t abase = sbu + buf*STAGE_BYTES;
    const uint32_t bbase = abase + BM*LDT*2;

    #pragma unroll
    for(int ks=0; ks<4; ks++){
      const int kk = ks*16;
      uint32_t afr[4][4], bfr[8][2];
      #pragma unroll
      for(int mi=0; mi<4; mi++)
        ldsm4(afr[mi][0], afr[mi][1], afr[mi][2], afr[mi][3],
              abase + (uint32_t)(aoff + mi*16*LDT + kk)*2);
      #pragma unroll
      for(int nip=0; nip<4; nip++)
        ldsm4(bfr[2*nip][0], bfr[2*nip][1], bfr[2*nip+1][0], bfr[2*nip+1][1],
              bbase + (uint32_t)(boff + nip*16*LDT + kk)*2);
      #pragma unroll
      for(int mi=0; mi<4; mi++)
        #pragma unroll
        for(int ni=0; ni<8; ni++)
          mma16816(acc[mi][ni], afr[mi], bfr[ni]);
    }
  }

  // epilogue
  #pragma unroll
  for(int mi=0; mi<4; mi++){
    int r0 = bm + wm + mi*16 + g;
    int r1 = r0 + 8;
    float sc0 = rowscale[r0]*wdeq;
    float sc1 = rowscale[r1]*wdeq;
    #pragma unroll
    for(int ni=0; ni<8; ni++){
      int col = bn + wn + ni*8 + 2*q;
      float x0 = acc[mi][ni][0]*sc0, x1 = acc[mi][ni][1]*sc0;
      float x2 = acc[mi][ni][2]*sc1, x3 = acc[mi][ni][3]*sc1;
      if(MODE == 0){
        x0 = (x0>0.f)? x0*x0 : 0.f;  x1 = (x1>0.f)? x1*x1 : 0.f;
        x2 = (x2>0.f)? x2*x2 : 0.f;  x3 = (x3>0.f)? x3*x3 : 0.f;
      } else if(MODE == 1){
        x0 = 1.f/(1.f+expf(-x0)); x1 = 1.f/(1.f+expf(-x1));
        x2 = 1.f/(1.f+expf(-x2)); x3 = 1.f/(1.f+expf(-x3));
      } else {
        float2 m0 = *(const float2*)&g_rbuf[(size_t)r0*Ndim + col];
        float2 m1 = *(const float2*)&g_rbuf[(size_t)r1*Ndim + col];
        x0 *= m0.x; x1 *= m0.y; x2 *= m1.x; x3 *= m1.y;
      }
      *(float2*)&C[(size_t)r0*Ndim + col] = make_float2(x0, x1);
      *(float2*)&C[(size_t)r1*Ndim + col] = make_float2(x2, x3);
    }
  }
}

// ---------------- launch ----------------
extern "C" void kernel_launch(void* const* d_in, const int* in_sizes, int n_in,
                              void* d_out, int out_size){
  const float* hidden = (const float*)d_in[0];
  const float* tmk    = (const float*)d_in[1];
  const float* tmr    = (const float*)d_in[2];
  const float* w_key  = (const float*)d_in[3];
  const float* w_rec  = (const float*)d_in[4];
  const float* w_val  = (const float*)d_in[5];
  const float* nk     = (const float*)d_in[6];
  const float* nr     = (const float*)d_in[7];
  const float* nv     = (const float*)d_in[8];
  float* out = (float*)d_out;

  cudaFuncSetAttribute(k_gemm<0>, cudaFuncAttributeMaxDynamicSharedMemorySize, SMEM_TOTAL);
  cudaFuncSetAttribute(k_gemm<1>, cudaFuncAttributeMaxDynamicSharedMemorySize, SMEM_TOTAL);
  cudaFuncSetAttribute(k_gemm<2>, cudaFuncAttributeMaxDynamicSharedMemorySize, SMEM_TOTAL);

  // 1) weight |w| partials (all 3 weights, one launch)
  k_absum_all<<<3072,256>>>(w_key, w_rec, w_val);

  // 2) ternary weight codes (ws reduced in-block)
  k_quantw_all<<<9216,256>>>(w_key, w_rec, w_val);

  // 3) token-shift mix + RMSNorm + int8 codes for key_in / rec_in
  k_actprep<<<M_,256>>>(hidden, tmk, tmr, nk, nr);

  // 4) key GEMM -> relu^2 -> k (fp32)
  k_gemm<0><<<dim3(F_/BN, M_/BM), NTHR, SMEM_TOTAL>>>(nullptr);

  // 5) RMSNorm + int8 codes for k
  k_quantK<<<M_,256>>>(nv);

  // 6) receptance GEMM -> sigmoid -> r
  k_gemm<1><<<dim3(H_/BN, M_/BM), NTHR, SMEM_TOTAL>>>(nullptr);

  // 7) value GEMM -> * r -> out
  k_gemm<2><<<dim3(H_/BN, M_/BM), NTHR, SMEM_TOTAL>>>(out);
}